// round 10
// baseline (speedup 1.0000x reference)
#include <cuda_runtime.h>
#include <cstdint>
#include <math.h>

#define NB      4
#define NGRID   512
#define NTARGET 1024
#define NBASIS  5
#define NCH     8

#define NWARP   16                // warps per CTA = grid chunks
#define CHUNK   (NGRID / NWARP)   // 32 grid points per warp
#define TILES   64                // 16-target tiles per batch
#define TPT     4                 // targets per thread
#define ROWF2   (NGRID + 2)       // padded row stride (float2)
#define STG     (4 * NBASIS * NCH + 8)  // 168 staged h floats per warp

// Polynomial exp2 on the FMA pipe (arg <= 0). Rel err ~3e-5.
__device__ __forceinline__ float ex2_poly(float a) {
    a = fmaxf(a, -120.0f);                    // guard exponent wrap
    float r = a + 12582912.0f;                // 1.5*2^23: round-to-int in mantissa
    float n = r - 12582912.0f;
    float f = a - n;                          // f in [-0.5, 0.5]
    float p = 0.0096181291f;
    p = fmaf(p, f, 0.0555041087f);
    p = fmaf(p, f, 0.2402265070f);
    p = fmaf(p, f, 0.6931471806f);
    p = fmaf(p, f, 1.0f);
    int ib = __float_as_int(r) << 23;         // == n << 23
    return __int_as_float(__float_as_int(p) + ib);
}
__device__ __forceinline__ float ex2_mufu(float a) {
    float w;
    asm("ex2.approx.ftz.f32 %0, %1;" : "=f"(w) : "f"(a));
    return w;
}

// ---------------------------------------------------------------------------
// Single kernel. CTA = 512 threads = 16 warps, one CTA per (b, 16-target
// tile), grid = 256. Warp w owns grid chunk [w*32, w*32+32); lane = c*4+ts
// covers all 8 channels x 4 target slots, TPT=4 -> 16 targets. One LDS.128
// feeds 8 exp evals (4 targets x 2 grid pts); 3 of 8 go through the FMA-pipe
// poly exp2, 5 through MUFU (pipe balancing). Chunk partials reduce in smem.
// ---------------------------------------------------------------------------
__global__ void __launch_bounds__(512)
finallayer_hyb(const float* __restrict__ x_grid,    // [NB][NGRID][NCH]
               const float* __restrict__ h_grid,    // [NB][NGRID][NBASIS][NCH]
               const float* __restrict__ target_x,  // [NB][NTARGET][NCH]
               const float* __restrict__ sigma,     // [NBASIS][NCH]
               const float* __restrict__ g_w,       // [1][NBASIS]
               const float* __restrict__ g_b,       // [1]
               float* __restrict__ out)             // [NB][NTARGET][NCH]
{
    __shared__ __align__(16) float2 pairs[NCH * ROWF2];  // (x*sc0, hsum0) ~33 KB
    __shared__ float s_stage[NWARP][STG];                // h stage ~10.8 KB
    __shared__ float s_part[NWARP][16 * NCH];            // chunk partials 8 KB
    __shared__ float s_sc[NCH][NBASIS];
    __shared__ int   s_grp[NCH][NBASIS];
    __shared__ int   s_nu[NCH];
    __shared__ float s_gw[NBASIS];

    const int tid  = threadIdx.x;
    const int tile = blockIdx.x & (TILES - 1);
    const int b    = blockIdx.x >> 6;

    // --- per-channel scale dedup (redundant per CTA, trivial) ---
    if (tid < NCH) {
        const float C = 0.8493218002880190f;  // sqrt(0.5 * log2(e))
        float s[NBASIS], uniq[NBASIS];
        int nu = 0;
#pragma unroll
        for (int k = 0; k < NBASIS; ++k)
            s[k] = expf(sigma[k * NCH + tid]) + 1e-6f;
#pragma unroll
        for (int k = 0; k < NBASIS; ++k) {
            int u = -1;
            for (int j = 0; j < nu; ++j)
                if (uniq[j] == s[k]) { u = j; break; }
            if (u < 0) { u = nu; uniq[nu++] = s[k]; }
            s_grp[tid][k] = u;
        }
        s_nu[tid] = nu;
        for (int u = 0; u < nu; ++u) s_sc[tid][u] = C / uniq[u];
    } else if (tid < NCH + NBASIS) {
        s_gw[tid - NCH] = g_w[tid - NCH];
    }
    __syncthreads();

    const int w    = tid >> 5;
    const int lane = tid & 31;

    // --- coalesced fill: warp w owns grid points [w*32, w*32+32) ---
    const float* xg = x_grid + b * (NGRID * NCH);
    const float* hg = h_grid + b * (NGRID * NBASIS * NCH);
    {
        const int cf = lane & 7;              // channel this lane folds
        const int gp = lane >> 3;             // local grid point 0..3
        const float sc0 = s_sc[cf][0];
#pragma unroll
        for (int blk = 0; blk < CHUNK / 4; ++blk) {
            const int g0 = w * CHUNK + blk * 4;           // 4 grid points
            const float* hb = hg + g0 * (NBASIS * NCH);   // 160 contiguous floats
#pragma unroll
            for (int j = 0; j < 5; ++j)                   // coalesced LDG
                s_stage[w][lane + 32 * j] = hb[lane + 32 * j];
            __syncwarp();
            float acc = 0.f;
#pragma unroll
            for (int k = 0; k < NBASIS; ++k)              // conflict-free LDS
                if (s_grp[cf][k] == 0)
                    acc += s_stage[w][gp * (NBASIS * NCH) + k * NCH + cf] * s_gw[k];
            float xv = xg[g0 * NCH + lane];               // coalesced
            pairs[cf * ROWF2 + g0 + gp] = make_float2(xv * sc0, acc);
            __syncwarp();
        }
    }
    __syncthreads();

    // --- main loop: lane = c*4 + tslot; targets tslot + 4j, j=0..3 ---
    const int c     = lane >> 2;
    const int tslot = lane & 3;

    float ts[TPT], acc[TPT];
    const float sc0 = s_sc[c][0];
#pragma unroll
    for (int j = 0; j < TPT; ++j) {
        int t = tile * 16 + tslot + 4 * j;
        ts[j]  = __ldg(&target_x[(b * NTARGET + t) * NCH + c]) * sc0;
        acc[j] = 0.f;
    }

    const float4* pc = (const float4*)(pairs + c * ROWF2) + w * (CHUNK / 2);
#pragma unroll
    for (int gg = 0; gg < CHUNK / 2; ++gg) {
        float4 q = pc[gg];                    // (x0*sc, h0, x1*sc, h1)
#pragma unroll
        for (int j = 0; j < TPT; ++j) {
            float d0 = q.x - ts[j];
            float d1 = q.z - ts[j];
            float a0 = -d0 * d0;
            float a1 = -d1 * d1;
            // 3 of 8 exponentials on the FMA pipe, 5 on MUFU
            float w0 = (j == 0)            ? ex2_poly(a0) : ex2_mufu(a0);
            float w1 = (j == 0 || j == 1)  ? ex2_poly(a1) : ex2_mufu(a1);
            acc[j] = fmaf(w0, q.y, acc[j]);
            acc[j] = fmaf(w1, q.w, acc[j]);
        }
    }

    // --- generic cold path: extra unique scales (not taken for uniform sigma) ---
    const int nu = s_nu[c];
    const int gc0 = w * CHUNK;
    for (int u = 1; u < nu; ++u) {
        const float sc = s_sc[c][u];
        for (int g = 0; g < CHUNK; ++g) {
            float xv = __ldg(&xg[(gc0 + g) * NCH + c]);
            float hv = 0.f;
#pragma unroll
            for (int k = 0; k < NBASIS; ++k)
                if (s_grp[c][k] == u)
                    hv += __ldg(&hg[((gc0 + g) * NBASIS + k) * NCH + c]) * s_gw[k];
            float xs = xv * sc;
#pragma unroll
            for (int j = 0; j < TPT; ++j) {
                float tvs = __ldg(&target_x[(b * NTARGET + tile * 16 + tslot + 4 * j) * NCH + c]);
                float ds  = xs - tvs * sc;
                acc[j] = fmaf(ex2_mufu(-ds * ds), hv, acc[j]);
            }
        }
    }

    // --- intra-CTA reduction over the 16 chunks ---
#pragma unroll
    for (int j = 0; j < TPT; ++j)
        s_part[w][(tslot + 4 * j) * NCH + c] = acc[j];
    __syncthreads();

    if (tid < 16 * NCH) {                     // tid = t_local*8 + c
        float sum = __ldg(g_b);
#pragma unroll
        for (int s = 0; s < NWARP; ++s)       // fixed order -> deterministic
            sum += s_part[s][tid];
        out[(b * NTARGET + tile * 16) * NCH + tid] = sum;  // coalesced
    }
}

// ---------------------------------------------------------------------------
extern "C" void kernel_launch(void* const* d_in, const int* in_sizes, int n_in,
                              void* d_out, int out_size) {
    const float* x_grid   = (const float*)d_in[0];  // [4,512,8]
    const float* h_grid   = (const float*)d_in[1];  // [4,512,5,8]
    const float* target_x = (const float*)d_in[2];  // [4,1024,8]
    const float* sigma    = (const float*)d_in[3];  // [5,8]
    const float* g_w      = (const float*)d_in[4];  // [1,5]
    const float* g_b      = (const float*)d_in[5];  // [1]
    float* out = (float*)d_out;                     // [4,1024,8]

    finallayer_hyb<<<NB * TILES, 512>>>(
        x_grid, h_grid, target_x, sigma, g_w, g_b, out);
}